// round 1
// baseline (speedup 1.0000x reference)
#include <cuda_runtime.h>
#include <cstdint>

#define BB 8
#define CC 16
#define FDIM 256
#define F2 129
#define TT 512
#define C2 32
#define HH 16
#define NT (BB*TT)

// ---------------- device scratch (static allocation allowed) ----------------
__device__ float g_zraw[(size_t)BB*C2*F2*TT];   // spectrum planes: (b, c2, k, t), real c=0..15, imag c=16..31
__device__ float g_y  [(size_t)NT*F2*C2];       // normalized LSTM input: (n, k, c2)
__device__ float g_h  [(size_t)NT*F2*C2];       // LSTM hidden cat(fwd,bwd): (n, k, 2H)
__device__ float g_P  [(size_t)BB*C2*F2*TT];    // product spectrum planes: (b, c2, k, t)
__device__ float g_mean[NT];
__device__ float g_rstd[NT];

__device__ __forceinline__ float sigf(float x) {
    return __fdividef(1.f, 1.f + __expf(-x));
}
__device__ __forceinline__ float tanhfast(float x) {
    // tanh(x) = 2*sigmoid(2x) - 1 ; __expf err ~2^-21, plenty for 1e-3
    return fmaf(2.f, __fdividef(1.f, 1.f + __expf(-2.f * x)), -1.f);
}

// ---------------- K1: forward rfft (256-pt radix-2, real input) --------------
__global__ void k_fft_fwd(const float* __restrict__ x) {
    int bc = blockIdx.x;             // (b*16 + c)
    int t0 = blockIdx.y * 32;
    int b = bc >> 4, c = bc & 15;
    __shared__ float st[258][33];    // staging: in rows 0..255, out rows 0..128 (re), 129..257 (im)
    __shared__ float wr[2][256], wi[2][256];
    int tid = threadIdx.x;

    for (int i = tid; i < 256 * 32; i += 256) {
        int f = i >> 5, tt = i & 31;
        st[f][tt] = x[((size_t)bc * 256 + f) * 512 + t0 + tt];
    }
    __syncthreads();

    int half = tid >> 7;             // which column of the pair
    int j = tid & 127;
    for (int pair = 0; pair < 16; ++pair) {
        int tt = pair * 2 + half;
        // bit-reversed load (real input)
        wr[half][__brev(j) >> 24] = st[j][tt];
        wi[half][__brev(j) >> 24] = 0.f;
        wr[half][__brev(j + 128) >> 24] = st[j + 128][tt];
        wi[half][__brev(j + 128) >> 24] = 0.f;
        __syncthreads();
        #pragma unroll
        for (int s = 1; s <= 8; ++s) {
            int hm = 1 << (s - 1), m = hm << 1;
            int g = j / hm, p = j - g * hm;
            int idx = g * m + p;
            float ang = -6.28318530717958647692f * (float)p / (float)m;
            float sv, cv; __sincosf(ang, &sv, &cv);
            float ar = wr[half][idx],      ai = wi[half][idx];
            float br = wr[half][idx + hm], bi = wi[half][idx + hm];
            float tr = br * cv - bi * sv;
            float ti = br * sv + bi * cv;
            wr[half][idx]      = ar + tr;  wi[half][idx]      = ai + ti;
            wr[half][idx + hm] = ar - tr;  wi[half][idx + hm] = ai - ti;
            __syncthreads();
        }
        // stash bins 0..128 back into staging column tt (inputs consumed)
        st[j][tt]       = wr[half][j];
        st[129 + j][tt] = wi[half][j];
        if (j == 0) { st[128][tt] = wr[half][128]; st[257][tt] = wi[half][128]; }
        __syncthreads();
    }

    for (int i = tid; i < 129 * 32; i += 256) {
        int k = i >> 5, tt = i & 31;
        g_zraw[(((size_t)b * 32 + c)      * 129 + k) * 512 + t0 + tt] = st[k][tt];
        g_zraw[(((size_t)b * 32 + 16 + c) * 129 + k) * 512 + t0 + tt] = st[129 + k][tt];
    }
}

// ---------------- K2: per-(b,t) mean / rstd over (2C, F2) --------------------
__global__ void k_stats() {
    // grid (8, 16), 512 threads; warp w sums e-chunk [w*258, w*258+258)
    __shared__ float s_sum[16][32], s_sq[16][32];
    int w = threadIdx.x >> 5, l = threadIdx.x & 31;
    int b = blockIdx.x;
    int t = blockIdx.y * 32 + l;
    const float* base = g_zraw + (size_t)b * 4128 * 512 + t;
    float sum = 0.f, sq = 0.f;
    int e0 = w * 258;
    #pragma unroll 4
    for (int e = e0; e < e0 + 258; ++e) {
        float v = base[(size_t)e * 512];
        sum += v;
        sq = fmaf(v, v, sq);
    }
    s_sum[w][l] = sum; s_sq[w][l] = sq;
    __syncthreads();
    if (threadIdx.x < 32) {
        int tt = blockIdx.y * 32 + threadIdx.x;
        float S = 0.f, Q = 0.f;
        #pragma unroll
        for (int i = 0; i < 16; ++i) { S += s_sum[i][threadIdx.x]; Q += s_sq[i][threadIdx.x]; }
        float mean = S * (1.f / 4128.f);
        float var = (Q - S * mean) * (1.f / 4127.f);   // ddof=1
        float rstd = __fdividef(1.f, sqrtf(fmaxf(var, 0.f)) + 1e-8f);
        g_mean[b * 512 + tt] = mean;
        g_rstd[b * 512 + tt] = rstd;
    }
}

// ---------------- K3: normalize + transpose to (n, k, c2) --------------------
__global__ void k_norm_transpose(const float* __restrict__ nw, const float* __restrict__ nb) {
    int k = blockIdx.x, t0 = blockIdx.y * 32, b = blockIdx.z;
    __shared__ float zs[32][33];
    __shared__ float nws[32], nbs[32];
    int tid = threadIdx.x;
    if (tid < 32) { nws[tid] = nw[tid * 129 + k]; nbs[tid] = nb[tid * 129 + k]; }
    for (int i = tid; i < 32 * 32; i += 256) {
        int c2 = i >> 5, tt = i & 31;
        zs[c2][tt] = g_zraw[(((size_t)b * 32 + c2) * 129 + k) * 512 + t0 + tt];
    }
    __syncthreads();
    for (int i = tid; i < 32 * 32; i += 256) {
        int tt = i >> 5, c2 = i & 31;
        int n = b * 512 + t0 + tt;
        float v = (zs[c2][tt] - g_mean[n]) * g_rstd[n] * nws[c2] + nbs[c2];
        g_y[((size_t)n * 129 + k) * 32 + c2] = v;
    }
}

// ---------------- K4: bidirectional LSTM, one warp per (seq, dir) ------------
__global__ void __launch_bounds__(256) k_lstm(
    const float* __restrict__ wihf, const float* __restrict__ whhf,
    const float* __restrict__ bihf, const float* __restrict__ bhhf,
    const float* __restrict__ wihb, const float* __restrict__ whhb,
    const float* __restrict__ bihb, const float* __restrict__ bhhb) {
    int wg = blockIdx.x * 8 + (threadIdx.x >> 5);
    int lane = threadIdx.x & 31;
    int n = wg >> 1, dir = wg & 1;

    const float* wih = dir ? wihb : wihf;
    const float* whh = dir ? whhb : whhf;
    const float* bih = dir ? bihb : bihf;
    const float* bhh = dir ? bhhb : bhhf;

    // lane j owns gate rows j and j+32 (i,f | g,o split across lanes)
    float wi0[32], wi1[32], wh0[16], wh1[16];
    #pragma unroll
    for (int q = 0; q < 32; ++q) { wi0[q] = wih[lane * 32 + q]; wi1[q] = wih[(lane + 32) * 32 + q]; }
    #pragma unroll
    for (int q = 0; q < 16; ++q) { wh0[q] = whh[lane * 16 + q]; wh1[q] = whh[(lane + 32) * 16 + q]; }
    float b0 = bih[lane] + bhh[lane];
    float b1 = bih[lane + 32] + bhh[lane + 32];

    float h = 0.f, cst = 0.f;   // lane m<16 owns hidden unit m
    const float* ybase = g_y + (size_t)n * 129 * 32;
    float* hbase = g_h + (size_t)n * 129 * 32 + dir * 16;

    for (int s = 0; s < 129; ++s) {
        int k = dir ? (128 - s) : s;
        float yv = ybase[k * 32 + lane];
        float a0 = b0, a1 = b1;
        #pragma unroll
        for (int q = 0; q < 32; ++q) {
            float v = __shfl_sync(0xffffffffu, yv, q);
            a0 = fmaf(v, wi0[q], a0);
            a1 = fmaf(v, wi1[q], a1);
        }
        #pragma unroll
        for (int q = 0; q < 16; ++q) {
            float hv = __shfl_sync(0xffffffffu, h, q);
            a0 = fmaf(hv, wh0[q], a0);
            a1 = fmaf(hv, wh1[q], a1);
        }
        // lane m<16: a0=i_m, a1=g_m ; lane m+16: a0=f_m, a1=o_m
        float fo0 = __shfl_xor_sync(0xffffffffu, a0, 16);
        float fo1 = __shfl_xor_sync(0xffffffffu, a1, 16);
        if (lane < 16) {
            float ig = sigf(a0);
            float gg = tanhfast(a1);
            float ff = sigf(fo0);
            float oo = sigf(fo1);
            cst = fmaf(ff, cst, ig * gg);
            h = oo * tanhfast(cst);
            hbase[k * 32 + lane] = h;
        }
    }
}

// ---------------- K5: linear(2H->2C) + complex multiply with x_fft -----------
__global__ void k_lin_cmul(const float* __restrict__ lw, const float* __restrict__ lb) {
    int k = blockIdx.x, t0 = blockIdx.y * 32, b = blockIdx.z;
    __shared__ float hs[32][33];    // [t][j]
    __shared__ float lws[32][32];   // [c2][j]
    __shared__ float lbs[32];
    __shared__ float yls[32][33];   // [c2][t]
    int tid = threadIdx.x;

    for (int i = tid; i < 1024; i += 256) lws[i >> 5][i & 31] = lw[i];
    if (tid < 32) lbs[tid] = lb[tid];
    for (int i = tid; i < 1024; i += 256) {
        int tt = i >> 5, j = i & 31;
        hs[tt][j] = g_h[(((size_t)(b * 512 + t0 + tt)) * 129 + k) * 32 + j];
    }
    __syncthreads();

    int tt = tid & 31, g = tid >> 5;
    #pragma unroll
    for (int ci = 0; ci < 4; ++ci) {
        int c2 = g + ci * 8;
        float acc = lbs[c2];
        #pragma unroll
        for (int j = 0; j < 32; ++j) acc = fmaf(hs[tt][j], lws[c2][j], acc);
        yls[c2][tt] = acc;
    }
    __syncthreads();

    size_t basez = ((size_t)(b * 32) * 129 + k) * 512 + t0 + tt;
    const size_t ps = (size_t)129 * 512;   // plane stride
    #pragma unroll
    for (int ci = 0; ci < 4; ++ci) {
        int c2 = g + ci * 8;
        if (c2 < 16) {
            float xr = g_zraw[basez + (size_t)c2 * ps];
            float xi = g_zraw[basez + (size_t)(c2 + 16) * ps];
            float yr = yls[c2][tt], yi = yls[c2 + 16][tt];
            g_P[basez + (size_t)c2 * ps] = yr * xr - yi * xi;
        } else {
            int c = c2 - 16;
            float xr = g_zraw[basez + (size_t)c * ps];
            float xi = g_zraw[basez + (size_t)c2 * ps];
            float yr = yls[c][tt], yi = yls[c2][tt];
            g_P[basez + (size_t)c2 * ps] = yr * xi + yi * xr;
        }
    }
}

// ---------------- K6: irfft (Hermitian extend + inverse 256-pt FFT) ----------
__global__ void k_fft_inv(float* __restrict__ out) {
    int bc = blockIdx.x;
    int t0 = blockIdx.y * 32;
    int b = bc >> 4, c = bc & 15;
    __shared__ float st[258][33];
    __shared__ float wr[2][256], wi[2][256];
    int tid = threadIdx.x;

    for (int i = tid; i < 129 * 32; i += 256) {
        int k = i >> 5, tt = i & 31;
        st[k][tt]       = g_P[(((size_t)b * 32 + c)      * 129 + k) * 512 + t0 + tt];
        st[129 + k][tt] = g_P[(((size_t)b * 32 + 16 + c) * 129 + k) * 512 + t0 + tt];
    }
    __syncthreads();

    int half = tid >> 7;
    int j = tid & 127;
    for (int pair = 0; pair < 16; ++pair) {
        int tt = pair * 2 + half;
        // Hermitian-extended bit-reversed load
        {
            float sr = st[j][tt], si = st[129 + j][tt];      // bins 0..127
            wr[half][__brev(j) >> 24] = sr;
            wi[half][__brev(j) >> 24] = si;
            int j2 = j + 128;                                 // bins 128..255
            float sr2, si2;
            if (j2 == 128) { sr2 = st[128][tt]; si2 = st[257][tt]; }
            else           { sr2 = st[256 - j2][tt]; si2 = -st[129 + 256 - j2][tt]; }
            wr[half][__brev(j2) >> 24] = sr2;
            wi[half][__brev(j2) >> 24] = si2;
        }
        __syncthreads();
        #pragma unroll
        for (int s = 1; s <= 8; ++s) {
            int hm = 1 << (s - 1), m = hm << 1;
            int g = j / hm, p = j - g * hm;
            int idx = g * m + p;
            float ang = 6.28318530717958647692f * (float)p / (float)m;  // +sign: inverse
            float sv, cv; __sincosf(ang, &sv, &cv);
            float ar = wr[half][idx],      ai = wi[half][idx];
            float br = wr[half][idx + hm], bi = wi[half][idx + hm];
            float tr = br * cv - bi * sv;
            float ti = br * sv + bi * cv;
            wr[half][idx]      = ar + tr;  wi[half][idx]      = ai + ti;
            wr[half][idx + hm] = ar - tr;  wi[half][idx + hm] = ai - ti;
            __syncthreads();
        }
        // real part -> staging rows 0..255 of column tt
        st[j][tt]       = wr[half][j];
        st[j + 128][tt] = wr[half][j + 128];
        __syncthreads();
    }

    const float inv = 1.f / 256.f;
    for (int i = tid; i < 256 * 32; i += 256) {
        int f = i >> 5, tt = i & 31;
        out[((size_t)bc * 256 + f) * 512 + t0 + tt] = st[f][tt] * inv;
    }
}

// ---------------- launcher ---------------------------------------------------
extern "C" void kernel_launch(void* const* d_in, const int* in_sizes, int n_in,
                              void* d_out, int out_size) {
    const float* x    = (const float*)d_in[0];
    const float* nw   = (const float*)d_in[1];
    const float* nb   = (const float*)d_in[2];
    const float* wihf = (const float*)d_in[3];
    const float* whhf = (const float*)d_in[4];
    const float* bihf = (const float*)d_in[5];
    const float* bhhf = (const float*)d_in[6];
    const float* wihb = (const float*)d_in[7];
    const float* whhb = (const float*)d_in[8];
    const float* bihb = (const float*)d_in[9];
    const float* bhhb = (const float*)d_in[10];
    const float* lw   = (const float*)d_in[11];
    const float* lb   = (const float*)d_in[12];
    float* out = (float*)d_out;

    k_fft_fwd<<<dim3(128, 16), 256>>>(x);
    k_stats<<<dim3(8, 16), 512>>>();
    k_norm_transpose<<<dim3(129, 16, 8), 256>>>(nw, nb);
    k_lstm<<<1024, 256>>>(wihf, whhf, bihf, bhhf, wihb, whhb, bihb, bhhb);
    k_lin_cmul<<<dim3(129, 16, 8), 256>>>(lw, lb);
    k_fft_inv<<<dim3(128, 16), 256>>>(out);
}